// round 13
// baseline (speedup 1.0000x reference)
#include <cuda_runtime.h>

// RNN_13855564496941: Euler RNN, T=1024, B=4096, H=50.
// R13: quad-group fat warps (8 cols/warp).
//   Warp = 8 batch cols as FOUR independent 2-col groups (A..D) sharing ONE
//   weight-register copy (50 f32x2). 8 independent 50-deep FFMA2 chains;
//   per k: 4 broadcast LDS.128 + 16 FFMA2 (32 issue-cyc covers LDS lat 29).
//   512 one-warp CTAs. Jrec@1 folded into bias (acts = tanh(h)).
//   Two LDG.128 per step fetch x for all 8 cols. Batched sOut flush uses all
//   32 lanes (8 rows x 4 groups). Else per R9..R12: cross-packed P/Q state,
//   non-duplicated act quads, tanh.approx, one __syncwarp/step.

namespace {
constexpr int T_STEPS = 1024;
constexpr int B_DIM   = 4096;
constexpr int H_DIM   = 50;
constexpr int KPAIR   = 25;        // float4 act entries (2 rows each)
constexpr int NGRP    = 4;         // 2-col groups per warp
constexpr int GRID    = B_DIM / (2 * NGRP);   // 512 CTAs
constexpr float DT    = 0.1f;
constexpr float OMDT  = 0.9f;
}

__device__ __forceinline__ float2 ffma2(float2 a, float2 b, float2 c) {
    unsigned long long A, B, C, D;
    __builtin_memcpy(&A, &a, 8);
    __builtin_memcpy(&B, &b, 8);
    __builtin_memcpy(&C, &c, 8);
    asm("fma.rn.f32x2 %0, %1, %2, %3;" : "=l"(D) : "l"(A), "l"(B), "l"(C));
    float2 d;
    __builtin_memcpy(&d, &D, 8);
    return d;
}

__device__ __forceinline__ float2 fadd2(float2 a, float2 b) {
    unsigned long long A, B, D;
    __builtin_memcpy(&A, &a, 8);
    __builtin_memcpy(&B, &b, 8);
    asm("add.rn.f32x2 %0, %1, %2;" : "=l"(D) : "l"(A), "l"(B));
    float2 d;
    __builtin_memcpy(&d, &D, 8);
    return d;
}

__device__ __forceinline__ float tanh_fast(float x) {
    float y;
    asm("tanh.approx.f32 %0, %1;" : "=f"(y) : "f"(x));
    return y;
}

__global__ __launch_bounds__(32) void rnn_persist(
    const float* __restrict__ inpt,   // (T, B)
    const float* __restrict__ Jin,    // (H, 1)
    const float* __restrict__ Jrec,   // (H, H)
    const float* __restrict__ Jout,   // (1, H)
    const float* __restrict__ bias,   // (H, 1)
    const float* __restrict__ h0,     // (H, B)
    float* __restrict__ out)          // (T, B)
{
    __shared__ float4 sAct[2][NGRP][32];    // [buf][group][lane]
    __shared__ float2 sOut[8][NGRP][33];    // [slot][group][lane], padded

    const int lane = threadIdx.x & 31;
    const int r    = 2 * lane;
    const bool valid = (lane < KPAIR);
    const int gc   = blockIdx.x * (2 * NGRP);   // group g owns cols gc+2g, gc+2g+1

    // weights + folded bias: bs = dt*bias + dt*Jrec@1
    float2 w[H_DIM];
    float2 bs = valid ? make_float2(DT * bias[r], DT * bias[r + 1]) : make_float2(0.f, 0.f);
    #pragma unroll
    for (int j = 0; j < H_DIM; j++) {
        float a = valid ? DT * Jrec[r * H_DIM + j]       : 0.0f;
        float b = valid ? DT * Jrec[(r + 1) * H_DIM + j] : 0.0f;
        w[j] = make_float2(a, b);
        bs = fadd2(bs, w[j]);
    }

    const float2 jin = valid ? make_float2(DT * Jin[r], DT * Jin[r + 1]) : make_float2(0.f, 0.f);
    const float2 jo  = valid ? make_float2(Jout[r],     Jout[r + 1])     : make_float2(0.f, 0.f);

    // cross-packed state per group: P=(h[r][c0], h[r+1][c1]), Q=(h[r][c1], h[r+1][c0])
    float2 P[NGRP], Q[NGRP];
    {
        float4 ra0 = valid ? *reinterpret_cast<const float4*>(&h0[r * B_DIM + gc])
                           : make_float4(0.f, 0.f, 0.f, 0.f);
        float4 ra1 = valid ? *reinterpret_cast<const float4*>(&h0[r * B_DIM + gc + 4])
                           : make_float4(0.f, 0.f, 0.f, 0.f);
        float4 rb0 = valid ? *reinterpret_cast<const float4*>(&h0[(r + 1) * B_DIM + gc])
                           : make_float4(0.f, 0.f, 0.f, 0.f);
        float4 rb1 = valid ? *reinterpret_cast<const float4*>(&h0[(r + 1) * B_DIM + gc + 4])
                           : make_float4(0.f, 0.f, 0.f, 0.f);
        P[0] = make_float2(ra0.x, rb0.y);  Q[0] = make_float2(ra0.y, rb0.x);
        P[1] = make_float2(ra0.z, rb0.w);  Q[1] = make_float2(ra0.w, rb0.z);
        P[2] = make_float2(ra1.x, rb1.y);  Q[2] = make_float2(ra1.y, rb1.x);
        P[3] = make_float2(ra1.z, rb1.w);  Q[3] = make_float2(ra1.w, rb1.z);
    }

    const float* xptr = inpt + gc;
    float4 xa = *reinterpret_cast<const float4*>(xptr);
    float4 xb = *reinterpret_cast<const float4*>(xptr + 4);
    int p = 0;

    for (int t = 0; t < T_STEPS; t++) {
        float4 xan = make_float4(0.f, 0.f, 0.f, 0.f);
        float4 xbn = make_float4(0.f, 0.f, 0.f, 0.f);
        if (t + 1 < T_STEPS) {
            xan = *reinterpret_cast<const float4*>(xptr + B_DIM);
            xbn = *reinterpret_cast<const float4*>(xptr + B_DIM + 4);
        }
        xptr += B_DIM;

        // acts = tanh(h): {a_r_c0, a_r_c1, a_{r+1}_c0, a_{r+1}_c1} per group
        #pragma unroll
        for (int g = 0; g < NGRP; g++)
            sAct[p][g][lane] = make_float4(tanh_fast(P[g].x), tanh_fast(Q[g].x),
                                           tanh_fast(Q[g].y), tanh_fast(P[g].y));

        // base terms before the barrier
        {
            const float2 om = make_float2(OMDT, OMDT);
            float xg0[NGRP] = {xa.x, xa.z, xb.x, xb.z};
            float xg1[NGRP] = {xa.y, xa.w, xb.y, xb.w};
            #pragma unroll
            for (int g = 0; g < NGRP; g++) {
                P[g] = ffma2(om, P[g], ffma2(jin, make_float2(xg0[g], xg1[g]), bs));
                Q[g] = ffma2(om, Q[g], ffma2(jin, make_float2(xg1[g], xg0[g]), bs));
            }
        }

        __syncwarp();

        // batched output flush (steps t-8..t-1): all 32 lanes, 8 rows x 4 groups
        if ((t & 7) == 0 && t > 0) {
            int g = lane >> 3, L = lane & 7;
            float2 s0 = sOut[L][g][0];
            float2 s1 = sOut[L][g][1];
            #pragma unroll
            for (int l = 2; l < KPAIR; l += 2) {
                s0 = fadd2(s0, sOut[L][g][l]);
                if (l + 1 < KPAIR) s1 = fadd2(s1, sOut[L][g][l + 1]);
            }
            *reinterpret_cast<float2*>(&out[(t - 8 + L) * B_DIM + gc + 2 * g]) = fadd2(s0, s1);
        }

        // matvec: per k, 4 broadcast LDS.128 + 16 FFMA2 over 8 indep chains
        #pragma unroll
        for (int k = 0; k < KPAIR; k++) {
            float4 av[NGRP];
            #pragma unroll
            for (int g = 0; g < NGRP; g++) av[g] = sAct[p][g][k];
            #pragma unroll
            for (int g = 0; g < NGRP; g++) {
                P[g] = ffma2(w[2 * k],     make_float2(av[g].x, av[g].y), P[g]);
                Q[g] = ffma2(w[2 * k],     make_float2(av[g].y, av[g].x), Q[g]);
            }
            #pragma unroll
            for (int g = 0; g < NGRP; g++) {
                P[g] = ffma2(w[2 * k + 1], make_float2(av[g].z, av[g].w), P[g]);
                Q[g] = ffma2(w[2 * k + 1], make_float2(av[g].w, av[g].z), Q[g]);
            }
        }

        // stage Jout partials
        #pragma unroll
        for (int g = 0; g < NGRP; g++)
            sOut[t & 7][g][lane] = make_float2(fmaf(jo.x, P[g].x, jo.y * Q[g].y),
                                               fmaf(jo.x, Q[g].x, jo.y * P[g].y));

        xa = xan;
        xb = xbn;
        p ^= 1;
    }

    // final flush (steps 1016..1023)
    __syncwarp();
    {
        int g = lane >> 3, L = lane & 7;
        float2 s0 = sOut[L][g][0];
        float2 s1 = sOut[L][g][1];
        #pragma unroll
        for (int l = 2; l < KPAIR; l += 2) {
            s0 = fadd2(s0, sOut[L][g][l]);
            if (l + 1 < KPAIR) s1 = fadd2(s1, sOut[L][g][l + 1]);
        }
        *reinterpret_cast<float2*>(&out[(T_STEPS - 8 + L) * B_DIM + gc + 2 * g]) = fadd2(s0, s1);
    }
}

extern "C" void kernel_launch(void* const* d_in, const int* in_sizes, int n_in,
                              void* d_out, int out_size) {
    const float* inpt = (const float*)d_in[0];
    const float* Jin  = (const float*)d_in[1];
    const float* Jrec = (const float*)d_in[2];
    const float* Jout = (const float*)d_in[3];
    const float* bias = (const float*)d_in[4];
    const float* h0   = (const float*)d_in[5];
    float* out = (float*)d_out;

    rnn_persist<<<GRID, 32>>>(inpt, Jin, Jrec, Jout, bias, h0, out);
}